// round 1
// baseline (speedup 1.0000x reference)
#include <cuda_runtime.h>

// MultiLayerGRU fused: 3 stacked GRU layers, T=1024, B=4096, I=5, H0=15, H1=10, H2=2.
// One warp per batch element; lanes own hidden units:
//   lanes  0..14 : layer-0 units
//   lanes 15..24 : layer-1 units
//   lanes 25..26 : layer-2 units (also write the output)
//   lanes 27..31 : x-feature loaders (prefetch x[t] into registers)
// Wavefront over layers: at iteration s, L0 computes h0(s), L1 computes h1(s-1),
// L2 computes h2(s-2). All cross-unit operands move via one shfl per k-step.
// Weights are register-resident per lane (gate rows r/z/n of its unit).

#define T_STEPS 1024
#define BATCH   4096
#define IN_DIM  5

__device__ __forceinline__ float fsig(float a) {
    // 1/(1+exp(-a)); __expf -> FMUL+MUFU.EX2, __fdividef -> MUFU.RCP+FMUL
    return __fdividef(1.0f, 1.0f + __expf(-a));
}
__device__ __forceinline__ float ftanh_(float v) {
    // tanh(v) = 1 - 2/(1+exp(2v)); saturates correctly at +/-inf of exp
    return 1.0f - 2.0f * __fdividef(1.0f, 1.0f + __expf(2.0f * v));
}

__global__ __launch_bounds__(128, 3)
void gru3_fused_kernel(
    const float* __restrict__ x,
    const float* __restrict__ w_ih0, const float* __restrict__ w_hh0,
    const float* __restrict__ b_ih0, const float* __restrict__ b_hh0,
    const float* __restrict__ w_ih1, const float* __restrict__ w_hh1,
    const float* __restrict__ b_ih1, const float* __restrict__ b_hh1,
    const float* __restrict__ w_ih2, const float* __restrict__ w_hh2,
    const float* __restrict__ b_ih2, const float* __restrict__ b_hh2,
    float* __restrict__ out)
{
    // ---- stage all weights into shared once (avoids scattered per-lane LDG) ----
    __shared__ float sw[1884];
    {
        int t = threadIdx.x;
        for (int i = t; i < 225; i += 128) sw[i]        = w_ih0[i];
        for (int i = t; i < 675; i += 128) sw[225 + i]  = w_hh0[i];
        for (int i = t; i <  45; i += 128) sw[900 + i]  = b_ih0[i];
        for (int i = t; i <  45; i += 128) sw[945 + i]  = b_hh0[i];
        for (int i = t; i < 450; i += 128) sw[990 + i]  = w_ih1[i];
        for (int i = t; i < 300; i += 128) sw[1440 + i] = w_hh1[i];
        for (int i = t; i <  30; i += 128) sw[1740 + i] = b_ih1[i];
        for (int i = t; i <  30; i += 128) sw[1770 + i] = b_hh1[i];
        for (int i = t; i <  60; i += 128) sw[1800 + i] = w_ih2[i];
        for (int i = t; i <  12; i += 128) sw[1860 + i] = w_hh2[i];
        for (int i = t; i <   6; i += 128) sw[1872 + i] = b_ih2[i];
        for (int i = t; i <   6; i += 128) sw[1878 + i] = b_hh2[i];
    }
    __syncthreads();
    const float* s_wih0 = sw;
    const float* s_whh0 = sw + 225;
    const float* s_bih0 = sw + 900;
    const float* s_bhh0 = sw + 945;
    const float* s_wih1 = sw + 990;
    const float* s_whh1 = sw + 1440;
    const float* s_bih1 = sw + 1740;
    const float* s_bhh1 = sw + 1770;
    const float* s_wih2 = sw + 1800;
    const float* s_whh2 = sw + 1860;
    const float* s_bih2 = sw + 1872;
    const float* s_bhh2 = sw + 1878;

    const int lane = threadIdx.x & 31;
    const int b    = blockIdx.x * (blockDim.x >> 5) + (threadIdx.x >> 5);

    // ---- per-lane register-resident weights ----
    // unified k-loop, k = 0..24:
    //   L0 lane: k 0..4 = x feature k          ; k 5..19  = h0 unit k-5
    //   L1 lane: k 0..14 = o0 unit k           ; k 15..24 = h1 unit k-15
    //   L2 lane: k 0..9  = o1 unit k           ; k 10..11 = h2 unit k-10
    // n-gate needs separate input/hidden parts: ani over k<15, anh over k>=5.
    float wr[25], wz[25], wni[15], wnh[20];
#pragma unroll
    for (int k = 0; k < 25; k++) { wr[k] = 0.f; wz[k] = 0.f; }
#pragma unroll
    for (int k = 0; k < 15; k++) wni[k] = 0.f;
#pragma unroll
    for (int k = 0; k < 20; k++) wnh[k] = 0.f;
    float br = 0.f, bz = 0.f, bni = 0.f, bnh = 0.f;

    if (lane < 15) {
        const int u = lane;
#pragma unroll
        for (int k = 0; k < 5; k++) {
            wr[k]  = s_wih0[u * 5 + k];
            wz[k]  = s_wih0[(15 + u) * 5 + k];
            wni[k] = s_wih0[(30 + u) * 5 + k];
        }
#pragma unroll
        for (int j = 0; j < 15; j++) {
            wr[5 + j]  = s_whh0[u * 15 + j];
            wz[5 + j]  = s_whh0[(15 + u) * 15 + j];
            wnh[j]     = s_whh0[(30 + u) * 15 + j];
        }
        br  = s_bih0[u] + s_bhh0[u];
        bz  = s_bih0[15 + u] + s_bhh0[15 + u];
        bni = s_bih0[30 + u];
        bnh = s_bhh0[30 + u];
    } else if (lane < 25) {
        const int u = lane - 15;
#pragma unroll
        for (int k = 0; k < 15; k++) {
            wr[k]  = s_wih1[u * 15 + k];
            wz[k]  = s_wih1[(10 + u) * 15 + k];
            wni[k] = s_wih1[(20 + u) * 15 + k];
        }
#pragma unroll
        for (int j = 0; j < 10; j++) {
            wr[15 + j]  = s_whh1[u * 10 + j];
            wz[15 + j]  = s_whh1[(10 + u) * 10 + j];
            wnh[10 + j] = s_whh1[(20 + u) * 10 + j];
        }
        br  = s_bih1[u] + s_bhh1[u];
        bz  = s_bih1[10 + u] + s_bhh1[10 + u];
        bni = s_bih1[20 + u];
        bnh = s_bhh1[20 + u];
    } else if (lane < 27) {
        const int u = lane - 25;
#pragma unroll
        for (int k = 0; k < 10; k++) {
            wr[k]  = s_wih2[u * 10 + k];
            wz[k]  = s_wih2[(2 + u) * 10 + k];
            wni[k] = s_wih2[(4 + u) * 10 + k];
        }
#pragma unroll
        for (int j = 0; j < 2; j++) {
            wr[10 + j]  = s_whh2[u * 2 + j];
            wz[10 + j]  = s_whh2[(2 + u) * 2 + j];
            wnh[5 + j]  = s_whh2[(4 + u) * 2 + j];
        }
        br  = s_bih2[u] + s_bhh2[u];
        bz  = s_bih2[2 + u] + s_bhh2[2 + u];
        bni = s_bih2[4 + u];
        bnh = s_bhh2[4 + u];
    }

    // shfl source lane for each k (t-invariant -> registers)
    int src[25];
#pragma unroll
    for (int k = 0; k < 25; k++) {
        int s0 = (k < 5) ? (27 + k) : (k - 5);                           // L0
        int s1 = k;                                                      // L1
        int s2 = (k < 10) ? (15 + k) : ((k < 12) ? (25 + k - 10) : 0);   // L2
        src[k] = (lane < 15) ? s0 : (lane < 25) ? s1 : (lane < 27) ? s2 : 0;
    }

    // wavefront delay per lane; loader lanes never commit
    const int d = (lane < 15) ? 0 : (lane < 25) ? 1 : (lane < 27) ? 2 : 0x40000000;
    const bool isOut = (lane == 25) || (lane == 26);

    const float* xp = x + (size_t)b * IN_DIM + ((lane >= 27) ? (lane - 27) : 0);
    float* op = out + (size_t)b * 2 + ((lane >= 25) ? (lane - 25) : 0);

    float sh = 0.f, xnext = 0.f, h = 0.f;
    if (lane >= 27) {
        sh    = xp[0];                       // x(0)
        xnext = xp[BATCH * IN_DIM];          // x(1)
    }

    for (int s = 0; s < T_STEPS + 2; ++s) {
        float ar = br, az = bz, ani = bni, anh = bnh;
#pragma unroll
        for (int k = 0; k < 25; k++) {
            float v = __shfl_sync(0xffffffffu, sh, src[k]);
            ar = fmaf(wr[k], v, ar);
            az = fmaf(wz[k], v, az);
            if (k < 15) ani = fmaf(wni[k], v, ani);
            if (k >= 5) anh = fmaf(wnh[k - 5], v, anh);
        }
        float r = fsig(ar);
        float z = fsig(az);
        float n = ftanh_(fmaf(r, anh, ani));
        float hnew = fmaf(z, h - n, n);      // (1-z)*n + z*h

        bool valid = (s >= d) && (s < T_STEPS + d);
        if (valid) h = hnew;
        if (valid && isOut) op[(size_t)(s - 2) * (BATCH * 2)] = hnew;

        if (lane < 27) {
            sh = h;
        } else {
            sh = xnext;                      // becomes x(s+1)
            int t2 = s + 2;
            xnext = (t2 < T_STEPS) ? xp[(size_t)t2 * (BATCH * IN_DIM)] : 0.f;
        }
    }
}

extern "C" void kernel_launch(void* const* d_in, const int* in_sizes, int n_in,
                              void* d_out, int out_size)
{
    (void)in_sizes; (void)n_in; (void)out_size;
    const float* x     = (const float*)d_in[0];
    const float* w_ih0 = (const float*)d_in[1];
    const float* w_hh0 = (const float*)d_in[2];
    const float* b_ih0 = (const float*)d_in[3];
    const float* b_hh0 = (const float*)d_in[4];
    const float* w_ih1 = (const float*)d_in[5];
    const float* w_hh1 = (const float*)d_in[6];
    const float* b_ih1 = (const float*)d_in[7];
    const float* b_hh1 = (const float*)d_in[8];
    const float* w_ih2 = (const float*)d_in[9];
    const float* w_hh2 = (const float*)d_in[10];
    const float* b_ih2 = (const float*)d_in[11];
    const float* b_hh2 = (const float*)d_in[12];

    // one warp per batch element: 4096 warps = 1024 blocks x 4 warps
    gru3_fused_kernel<<<BATCH / 4, 128>>>(
        x, w_ih0, w_hh0, b_ih0, b_hh0,
        w_ih1, w_hh1, b_ih1, b_hh1,
        w_ih2, w_hh2, b_ih2, b_hh2,
        (float*)d_out);
}

// round 2
// speedup vs baseline: 1.8652x; 1.8652x over previous
#include <cuda_runtime.h>

// MultiLayerGRU fused: 3 stacked GRU layers, T=1024, B=4096, I=5, H0=15, H1=10, H2=2.
// One warp per TWO batch elements (packed f32x2 lanes); lanes own hidden units:
//   lanes  0..14 : layer-0 units
//   lanes 15..24 : layer-1 units
//   lanes 25..26 : layer-2 units (write the output)
//   lanes 27..31 : x-feature loaders (prefetch x[t] into registers)
// Wavefront over layers: iteration s computes h0(s), h1(s-1), h2(s-2).
// All cross-unit operands move via one 64-bit shfl per k-step (packed batch pair).
// Dot products use fma.rn.f32x2: one instruction = 2 batches' MAC.
// shfl source: src_k = (base + k) mod 32, base in {27,0,15} per lane class
// (mod is free: __shfl_sync wraps srcLane).

#define T_STEPS 1024
#define BATCH   4096
#define IN_DIM  5

using u64 = unsigned long long;

__device__ __forceinline__ u64 pack2(float a, float b) {
    u64 r;
    asm("mov.b64 %0, {%1, %2};" : "=l"(r) : "f"(a), "f"(b));
    return r;
}
__device__ __forceinline__ void unpack2(u64 p, float& a, float& b) {
    asm("mov.b64 {%0, %1}, %2;" : "=f"(a), "=f"(b) : "l"(p));
}
__device__ __forceinline__ u64 fma2(u64 a, u64 b, u64 c) {
    u64 d;
    asm("fma.rn.f32x2 %0, %1, %2, %3;" : "=l"(d) : "l"(a), "l"(b), "l"(c));
    return d;
}

__device__ __forceinline__ float fsig(float a) {
    return __fdividef(1.0f, 1.0f + __expf(-a));
}
__device__ __forceinline__ float ftanh_(float v) {
    return 1.0f - 2.0f * __fdividef(1.0f, 1.0f + __expf(2.0f * v));
}

__global__ __launch_bounds__(128, 2)
void gru3_fused_kernel(
    const float* __restrict__ x,
    const float* __restrict__ w_ih0, const float* __restrict__ w_hh0,
    const float* __restrict__ b_ih0, const float* __restrict__ b_hh0,
    const float* __restrict__ w_ih1, const float* __restrict__ w_hh1,
    const float* __restrict__ b_ih1, const float* __restrict__ b_hh1,
    const float* __restrict__ w_ih2, const float* __restrict__ w_hh2,
    const float* __restrict__ b_ih2, const float* __restrict__ b_hh2,
    float* __restrict__ out)
{
    // ---- stage all weights into shared once ----
    __shared__ float sw[1884];
    {
        int t = threadIdx.x;
        for (int i = t; i < 225; i += 128) sw[i]        = w_ih0[i];
        for (int i = t; i < 675; i += 128) sw[225 + i]  = w_hh0[i];
        for (int i = t; i <  45; i += 128) sw[900 + i]  = b_ih0[i];
        for (int i = t; i <  45; i += 128) sw[945 + i]  = b_hh0[i];
        for (int i = t; i < 450; i += 128) sw[990 + i]  = w_ih1[i];
        for (int i = t; i < 300; i += 128) sw[1440 + i] = w_hh1[i];
        for (int i = t; i <  30; i += 128) sw[1740 + i] = b_ih1[i];
        for (int i = t; i <  30; i += 128) sw[1770 + i] = b_hh1[i];
        for (int i = t; i <  60; i += 128) sw[1800 + i] = w_ih2[i];
        for (int i = t; i <  12; i += 128) sw[1860 + i] = w_hh2[i];
        for (int i = t; i <   6; i += 128) sw[1872 + i] = b_ih2[i];
        for (int i = t; i <   6; i += 128) sw[1878 + i] = b_hh2[i];
    }
    __syncthreads();
    const float* s_wih0 = sw;
    const float* s_whh0 = sw + 225;
    const float* s_bih0 = sw + 900;
    const float* s_bhh0 = sw + 945;
    const float* s_wih1 = sw + 990;
    const float* s_whh1 = sw + 1440;
    const float* s_bih1 = sw + 1740;
    const float* s_bhh1 = sw + 1770;
    const float* s_wih2 = sw + 1800;
    const float* s_whh2 = sw + 1860;
    const float* s_bih2 = sw + 1872;
    const float* s_bhh2 = sw + 1878;

    const int lane = threadIdx.x & 31;
    const int gw   = blockIdx.x * (blockDim.x >> 5) + (threadIdx.x >> 5);
    const int b0   = gw * 2;           // batches b0, b0+1

    // ---- per-lane register-resident packed (w,w) weights ----
    // unified k-loop, k = 0..24 (see lane-class mapping in header comment).
    float wr[25], wz[25], wni[15], wnh[20];
#pragma unroll
    for (int k = 0; k < 25; k++) { wr[k] = 0.f; wz[k] = 0.f; }
#pragma unroll
    for (int k = 0; k < 15; k++) wni[k] = 0.f;
#pragma unroll
    for (int k = 0; k < 20; k++) wnh[k] = 0.f;
    float br = 0.f, bz = 0.f, bni = 0.f, bnh = 0.f;

    if (lane < 15) {
        const int u = lane;
#pragma unroll
        for (int k = 0; k < 5; k++) {
            wr[k]  = s_wih0[u * 5 + k];
            wz[k]  = s_wih0[(15 + u) * 5 + k];
            wni[k] = s_wih0[(30 + u) * 5 + k];
        }
#pragma unroll
        for (int j = 0; j < 15; j++) {
            wr[5 + j]  = s_whh0[u * 15 + j];
            wz[5 + j]  = s_whh0[(15 + u) * 15 + j];
            wnh[j]     = s_whh0[(30 + u) * 15 + j];
        }
        br  = s_bih0[u] + s_bhh0[u];
        bz  = s_bih0[15 + u] + s_bhh0[15 + u];
        bni = s_bih0[30 + u];
        bnh = s_bhh0[30 + u];
    } else if (lane < 25) {
        const int u = lane - 15;
#pragma unroll
        for (int k = 0; k < 15; k++) {
            wr[k]  = s_wih1[u * 15 + k];
            wz[k]  = s_wih1[(10 + u) * 15 + k];
            wni[k] = s_wih1[(20 + u) * 15 + k];
        }
#pragma unroll
        for (int j = 0; j < 10; j++) {
            wr[15 + j]  = s_whh1[u * 10 + j];
            wz[15 + j]  = s_whh1[(10 + u) * 10 + j];
            wnh[10 + j] = s_whh1[(20 + u) * 10 + j];
        }
        br  = s_bih1[u] + s_bhh1[u];
        bz  = s_bih1[10 + u] + s_bhh1[10 + u];
        bni = s_bih1[20 + u];
        bnh = s_bhh1[20 + u];
    } else if (lane < 27) {
        const int u = lane - 25;
#pragma unroll
        for (int k = 0; k < 10; k++) {
            wr[k]  = s_wih2[u * 10 + k];
            wz[k]  = s_wih2[(2 + u) * 10 + k];
            wni[k] = s_wih2[(4 + u) * 10 + k];
        }
#pragma unroll
        for (int j = 0; j < 2; j++) {
            wr[10 + j] = s_whh2[u * 2 + j];
            wz[10 + j] = s_whh2[(2 + u) * 2 + j];
            wnh[5 + j] = s_whh2[(4 + u) * 2 + j];
        }
        br  = s_bih2[u] + s_bhh2[u];
        bz  = s_bih2[2 + u] + s_bhh2[2 + u];
        bni = s_bih2[4 + u];
        bnh = s_bhh2[4 + u];
    }

    // duplicate-packed weights (w,w) for f32x2 FMA
    u64 wr2[25], wz2[25], wni2[15], wnh2[20];
#pragma unroll
    for (int k = 0; k < 25; k++) { wr2[k] = pack2(wr[k], wr[k]); wz2[k] = pack2(wz[k], wz[k]); }
#pragma unroll
    for (int k = 0; k < 15; k++) wni2[k] = pack2(wni[k], wni[k]);
#pragma unroll
    for (int k = 0; k < 20; k++) wnh2[k] = pack2(wnh[k], wnh[k]);
    const u64 br2  = pack2(br, br);
    const u64 bz2  = pack2(bz, bz);
    const u64 bni2 = pack2(bni, bni);
    const u64 bnh2 = pack2(bnh, bnh);

    // shfl base per lane class: src_k = base + k (shfl wraps mod 32)
    const int base = (lane < 15) ? 27 : (lane < 25) ? 0 : 15;

    // wavefront delay per lane; loader lanes never commit
    const int d = (lane < 15) ? 0 : (lane < 25) ? 1 : (lane < 27) ? 2 : 0x40000000;
    const bool isOut = (lane == 25) || (lane == 26);

    const int feat = (lane >= 27) ? (lane - 27) : 0;
    const float* xp0 = x + (size_t)b0 * IN_DIM + feat;
    const float* xp1 = x + (size_t)(b0 + 1) * IN_DIM + feat;
    const int u2 = (lane >= 25) ? (lane - 25) : 0;
    float* op0 = out + (size_t)b0 * 2 + u2;
    float* op1 = out + (size_t)(b0 + 1) * 2 + u2;

    float h0 = 0.f, h1 = 0.f;          // this lane's hidden state, batches 0/1
    float xn0 = 0.f, xn1 = 0.f;        // prefetched x(t+1)
    u64 sh = 0;                        // packed shared operand (b0, b1)
    if (lane >= 27) {
        sh  = pack2(xp0[0], xp1[0]);                           // x(0)
        xn0 = xp0[BATCH * IN_DIM];                             // x(1)
        xn1 = xp1[BATCH * IN_DIM];
    }

    for (int s = 0; s < T_STEPS + 2; ++s) {
        u64 ar = br2, az = bz2, ani = bni2, anh = bnh2;
#pragma unroll
        for (int k = 0; k < 25; k++) {
            u64 v = __shfl_sync(0xffffffffu, sh, base + k);    // wraps mod 32
            ar = fma2(wr2[k], v, ar);
            az = fma2(wz2[k], v, az);
            if (k < 15) ani = fma2(wni2[k], v, ani);
            if (k >= 5) anh = fma2(wnh2[k - 5], v, anh);
        }
        float arA, arB, azA, azB, aniA, aniB, anhA, anhB;
        unpack2(ar, arA, arB);
        unpack2(az, azA, azB);
        unpack2(ani, aniA, aniB);
        unpack2(anh, anhA, anhB);

        float rA = fsig(arA), rB = fsig(arB);
        float zA = fsig(azA), zB = fsig(azB);
        float nA = ftanh_(fmaf(rA, anhA, aniA));
        float nB = ftanh_(fmaf(rB, anhB, aniB));
        float hnA = fmaf(zA, h0 - nA, nA);                     // (1-z)*n + z*h
        float hnB = fmaf(zB, h1 - nB, nB);

        bool valid = (s >= d) && (s < T_STEPS + d);
        if (valid) { h0 = hnA; h1 = hnB; }
        if (valid && isOut) {
            op0[(size_t)(s - 2) * (BATCH * 2)] = hnA;
            op1[(size_t)(s - 2) * (BATCH * 2)] = hnB;
        }

        if (lane < 27) {
            sh = pack2(h0, h1);
        } else {
            sh = pack2(xn0, xn1);                              // becomes x(s+1)
            int t2 = s + 2;
            bool inb = (t2 < T_STEPS);
            xn0 = inb ? xp0[(size_t)t2 * (BATCH * IN_DIM)] : 0.f;
            xn1 = inb ? xp1[(size_t)t2 * (BATCH * IN_DIM)] : 0.f;
        }
    }
}

extern "C" void kernel_launch(void* const* d_in, const int* in_sizes, int n_in,
                              void* d_out, int out_size)
{
    (void)in_sizes; (void)n_in; (void)out_size;
    const float* x     = (const float*)d_in[0];
    const float* w_ih0 = (const float*)d_in[1];
    const float* w_hh0 = (const float*)d_in[2];
    const float* b_ih0 = (const float*)d_in[3];
    const float* b_hh0 = (const float*)d_in[4];
    const float* w_ih1 = (const float*)d_in[5];
    const float* w_hh1 = (const float*)d_in[6];
    const float* b_ih1 = (const float*)d_in[7];
    const float* b_hh1 = (const float*)d_in[8];
    const float* w_ih2 = (const float*)d_in[9];
    const float* w_hh2 = (const float*)d_in[10];
    const float* b_ih2 = (const float*)d_in[11];
    const float* b_hh2 = (const float*)d_in[12];

    // one warp per 2 batch elements: 2048 warps = 512 blocks x 4 warps
    gru3_fused_kernel<<<BATCH / 8, 128>>>(
        x, w_ih0, w_hh0, b_ih0, b_hh0,
        w_ih1, w_hh1, b_ih1, b_hh1,
        w_ih2, w_hh2, b_ih2, b_hh2,
        (float*)d_out);
}

// round 3
// speedup vs baseline: 2.5064x; 1.3438x over previous
#include <cuda_runtime.h>

// MultiLayerGRU fused: 3 stacked GRU layers, T=1024, B=4096, I=5, H0=15, H1=10, H2=2.
// One warp per FOUR batch elements: two independent f32x2 packed pairs per lane
// (weights are shared across pairs, so the 2nd pair costs only accumulator regs).
// Lane roles:
//   lanes  0..14 : layer-0 units
//   lanes 15..24 : layer-1 units
//   lanes 25..26 : layer-2 units (write the output)
//   lanes 27..31 : x-feature loaders (prefetch x[t] into registers)
// Wavefront over layers: iteration s computes h0(s), h1(s-1), h2(s-2).
// shfl source: src_k = (base + k) mod 32, base in {27,0,15} (shfl wraps srcLane).

#define T_STEPS 1024
#define BATCH   4096
#define IN_DIM  5

using u64 = unsigned long long;

__device__ __forceinline__ u64 pack2(float a, float b) {
    u64 r;
    asm("mov.b64 %0, {%1, %2};" : "=l"(r) : "f"(a), "f"(b));
    return r;
}
__device__ __forceinline__ void unpack2(u64 p, float& a, float& b) {
    asm("mov.b64 {%0, %1}, %2;" : "=f"(a), "=f"(b) : "l"(p));
}
__device__ __forceinline__ u64 fma2(u64 a, u64 b, u64 c) {
    u64 d;
    asm("fma.rn.f32x2 %0, %1, %2, %3;" : "=l"(d) : "l"(a), "l"(b), "l"(c));
    return d;
}

__device__ __forceinline__ float fsig(float a) {
    return __fdividef(1.0f, 1.0f + __expf(-a));
}
__device__ __forceinline__ float ftanh_(float v) {
    return 1.0f - 2.0f * __fdividef(1.0f, 1.0f + __expf(2.0f * v));
}

__global__ __launch_bounds__(128, 2)
void gru3_fused_kernel(
    const float* __restrict__ x,
    const float* __restrict__ w_ih0, const float* __restrict__ w_hh0,
    const float* __restrict__ b_ih0, const float* __restrict__ b_hh0,
    const float* __restrict__ w_ih1, const float* __restrict__ w_hh1,
    const float* __restrict__ b_ih1, const float* __restrict__ b_hh1,
    const float* __restrict__ w_ih2, const float* __restrict__ w_hh2,
    const float* __restrict__ b_ih2, const float* __restrict__ b_hh2,
    float* __restrict__ out)
{
    // ---- stage all weights into shared once ----
    __shared__ float sw[1884];
    {
        int t = threadIdx.x;
        for (int i = t; i < 225; i += 128) sw[i]        = w_ih0[i];
        for (int i = t; i < 675; i += 128) sw[225 + i]  = w_hh0[i];
        for (int i = t; i <  45; i += 128) sw[900 + i]  = b_ih0[i];
        for (int i = t; i <  45; i += 128) sw[945 + i]  = b_hh0[i];
        for (int i = t; i < 450; i += 128) sw[990 + i]  = w_ih1[i];
        for (int i = t; i < 300; i += 128) sw[1440 + i] = w_hh1[i];
        for (int i = t; i <  30; i += 128) sw[1740 + i] = b_ih1[i];
        for (int i = t; i <  30; i += 128) sw[1770 + i] = b_hh1[i];
        for (int i = t; i <  60; i += 128) sw[1800 + i] = w_ih2[i];
        for (int i = t; i <  12; i += 128) sw[1860 + i] = w_hh2[i];
        for (int i = t; i <   6; i += 128) sw[1872 + i] = b_ih2[i];
        for (int i = t; i <   6; i += 128) sw[1878 + i] = b_hh2[i];
    }
    __syncthreads();
    const float* s_wih0 = sw;
    const float* s_whh0 = sw + 225;
    const float* s_bih0 = sw + 900;
    const float* s_bhh0 = sw + 945;
    const float* s_wih1 = sw + 990;
    const float* s_whh1 = sw + 1440;
    const float* s_bih1 = sw + 1740;
    const float* s_bhh1 = sw + 1770;
    const float* s_wih2 = sw + 1800;
    const float* s_whh2 = sw + 1860;
    const float* s_bih2 = sw + 1872;
    const float* s_bhh2 = sw + 1878;

    const int lane = threadIdx.x & 31;
    const int gw   = blockIdx.x * (blockDim.x >> 5) + (threadIdx.x >> 5);
    const int b0   = gw * 4;           // batches b0 .. b0+3

    // ---- per-lane register-resident weights (unified k-loop, k = 0..24) ----
    float wr[25], wz[25], wni[15], wnh[20];
#pragma unroll
    for (int k = 0; k < 25; k++) { wr[k] = 0.f; wz[k] = 0.f; }
#pragma unroll
    for (int k = 0; k < 15; k++) wni[k] = 0.f;
#pragma unroll
    for (int k = 0; k < 20; k++) wnh[k] = 0.f;
    float br = 0.f, bz = 0.f, bni = 0.f, bnh = 0.f;

    if (lane < 15) {
        const int u = lane;
#pragma unroll
        for (int k = 0; k < 5; k++) {
            wr[k]  = s_wih0[u * 5 + k];
            wz[k]  = s_wih0[(15 + u) * 5 + k];
            wni[k] = s_wih0[(30 + u) * 5 + k];
        }
#pragma unroll
        for (int j = 0; j < 15; j++) {
            wr[5 + j]  = s_whh0[u * 15 + j];
            wz[5 + j]  = s_whh0[(15 + u) * 15 + j];
            wnh[j]     = s_whh0[(30 + u) * 15 + j];
        }
        br  = s_bih0[u] + s_bhh0[u];
        bz  = s_bih0[15 + u] + s_bhh0[15 + u];
        bni = s_bih0[30 + u];
        bnh = s_bhh0[30 + u];
    } else if (lane < 25) {
        const int u = lane - 15;
#pragma unroll
        for (int k = 0; k < 15; k++) {
            wr[k]  = s_wih1[u * 15 + k];
            wz[k]  = s_wih1[(10 + u) * 15 + k];
            wni[k] = s_wih1[(20 + u) * 15 + k];
        }
#pragma unroll
        for (int j = 0; j < 10; j++) {
            wr[15 + j]  = s_whh1[u * 10 + j];
            wz[15 + j]  = s_whh1[(10 + u) * 10 + j];
            wnh[10 + j] = s_whh1[(20 + u) * 10 + j];
        }
        br  = s_bih1[u] + s_bhh1[u];
        bz  = s_bih1[10 + u] + s_bhh1[10 + u];
        bni = s_bih1[20 + u];
        bnh = s_bhh1[20 + u];
    } else if (lane < 27) {
        const int u = lane - 25;
#pragma unroll
        for (int k = 0; k < 10; k++) {
            wr[k]  = s_wih2[u * 10 + k];
            wz[k]  = s_wih2[(2 + u) * 10 + k];
            wni[k] = s_wih2[(4 + u) * 10 + k];
        }
#pragma unroll
        for (int j = 0; j < 2; j++) {
            wr[10 + j] = s_whh2[u * 2 + j];
            wz[10 + j] = s_whh2[(2 + u) * 2 + j];
            wnh[5 + j] = s_whh2[(4 + u) * 2 + j];
        }
        br  = s_bih2[u] + s_bhh2[u];
        bz  = s_bih2[2 + u] + s_bhh2[2 + u];
        bni = s_bih2[4 + u];
        bnh = s_bhh2[4 + u];
    }

    // duplicate-packed weights (w,w) for f32x2 FMA — shared by both batch pairs
    u64 wr2[25], wz2[25], wni2[15], wnh2[20];
#pragma unroll
    for (int k = 0; k < 25; k++) { wr2[k] = pack2(wr[k], wr[k]); wz2[k] = pack2(wz[k], wz[k]); }
#pragma unroll
    for (int k = 0; k < 15; k++) wni2[k] = pack2(wni[k], wni[k]);
#pragma unroll
    for (int k = 0; k < 20; k++) wnh2[k] = pack2(wnh[k], wnh[k]);
    const u64 br2  = pack2(br, br);
    const u64 bz2  = pack2(bz, bz);
    const u64 bni2 = pack2(bni, bni);
    const u64 bnh2 = pack2(bnh, bnh);

    // shfl base per lane class: src_k = base + k (shfl wraps mod 32)
    const int base = (lane < 15) ? 27 : (lane < 25) ? 0 : 15;

    // wavefront delay per lane; loader lanes never commit
    const int d = (lane < 15) ? 0 : (lane < 25) ? 1 : (lane < 27) ? 2 : 0x40000000;
    const bool isOut = (lane == 25) || (lane == 26);

    // single base pointers; adjacent batches are immediate offsets (j*IN_DIM / j*2)
    const int feat = (lane >= 27) ? (lane - 27) : 0;
    const float* xp = x + (size_t)b0 * IN_DIM + feat;
    const int u2 = (lane >= 25) ? (lane - 25) : 0;
    float* op = out + (size_t)b0 * 2 + u2;

    float h[4] = {0.f, 0.f, 0.f, 0.f};   // hidden state, 4 batches
    float xn[4] = {0.f, 0.f, 0.f, 0.f};  // prefetched x(t+1)
    u64 sh0 = 0, sh1 = 0;                // packed shared operands (b0,b1) / (b2,b3)
    if (lane >= 27) {
        sh0 = pack2(xp[0 * IN_DIM], xp[1 * IN_DIM]);             // x(0)
        sh1 = pack2(xp[2 * IN_DIM], xp[3 * IN_DIM]);
#pragma unroll
        for (int j = 0; j < 4; j++) xn[j] = xp[BATCH * IN_DIM + j * IN_DIM];  // x(1)
    }

    for (int s = 0; s < T_STEPS + 2; ++s) {
        u64 ar0 = br2, az0 = bz2, ani0 = bni2, anh0 = bnh2;
        u64 ar1 = br2, az1 = bz2, ani1 = bni2, anh1 = bnh2;
#pragma unroll
        for (int k = 0; k < 25; k++) {
            u64 v0 = __shfl_sync(0xffffffffu, sh0, base + k);    // wraps mod 32
            u64 v1 = __shfl_sync(0xffffffffu, sh1, base + k);
            ar0 = fma2(wr2[k], v0, ar0);
            ar1 = fma2(wr2[k], v1, ar1);
            az0 = fma2(wz2[k], v0, az0);
            az1 = fma2(wz2[k], v1, az1);
            if (k < 15) { ani0 = fma2(wni2[k], v0, ani0); ani1 = fma2(wni2[k], v1, ani1); }
            if (k >= 5) { anh0 = fma2(wnh2[k - 5], v0, anh0); anh1 = fma2(wnh2[k - 5], v1, anh1); }
        }

        float arf[4], azf[4], anif[4], anhf[4], hn[4];
        unpack2(ar0, arf[0], arf[1]);   unpack2(ar1, arf[2], arf[3]);
        unpack2(az0, azf[0], azf[1]);   unpack2(az1, azf[2], azf[3]);
        unpack2(ani0, anif[0], anif[1]); unpack2(ani1, anif[2], anif[3]);
        unpack2(anh0, anhf[0], anhf[1]); unpack2(anh1, anhf[2], anhf[3]);
#pragma unroll
        for (int j = 0; j < 4; j++) {
            float r = fsig(arf[j]);
            float z = fsig(azf[j]);
            float n = ftanh_(fmaf(r, anhf[j], anif[j]));
            hn[j] = fmaf(z, h[j] - n, n);                        // (1-z)*n + z*h
        }

        bool valid = (s >= d) && (s < T_STEPS + d);
        if (valid) {
#pragma unroll
            for (int j = 0; j < 4; j++) h[j] = hn[j];
        }
        if (valid && isOut) {
            size_t o = (size_t)(s - 2) * (BATCH * 2);
#pragma unroll
            for (int j = 0; j < 4; j++) op[o + j * 2] = hn[j];
        }

        if (lane < 27) {
            sh0 = pack2(h[0], h[1]);
            sh1 = pack2(h[2], h[3]);
        } else {
            sh0 = pack2(xn[0], xn[1]);                           // becomes x(s+1)
            sh1 = pack2(xn[2], xn[3]);
            int t2 = s + 2;
            bool inb = (t2 < T_STEPS);
            size_t xo = (size_t)t2 * (BATCH * IN_DIM);
#pragma unroll
            for (int j = 0; j < 4; j++) xn[j] = inb ? xp[xo + j * IN_DIM] : 0.f;
        }
    }
}

extern "C" void kernel_launch(void* const* d_in, const int* in_sizes, int n_in,
                              void* d_out, int out_size)
{
    (void)in_sizes; (void)n_in; (void)out_size;
    const float* x     = (const float*)d_in[0];
    const float* w_ih0 = (const float*)d_in[1];
    const float* w_hh0 = (const float*)d_in[2];
    const float* b_ih0 = (const float*)d_in[3];
    const float* b_hh0 = (const float*)d_in[4];
    const float* w_ih1 = (const float*)d_in[5];
    const float* w_hh1 = (const float*)d_in[6];
    const float* b_ih1 = (const float*)d_in[7];
    const float* b_hh1 = (const float*)d_in[8];
    const float* w_ih2 = (const float*)d_in[9];
    const float* w_hh2 = (const float*)d_in[10];
    const float* b_ih2 = (const float*)d_in[11];
    const float* b_hh2 = (const float*)d_in[12];

    // one warp per 4 batch elements: 1024 warps = 256 blocks x 4 warps
    gru3_fused_kernel<<<BATCH / 16, 128>>>(
        x, w_ih0, w_hh0, b_ih0, b_hh0,
        w_ih1, w_hh1, b_ih1, b_hh1,
        w_ih2, w_hh2, b_ih2, b_hh2,
        (float*)d_out);
}